// round 5
// baseline (speedup 1.0000x reference)
#include <cuda_runtime.h>

#define NN 131072
#define EE 2097152
#define GB 8
#define CWD 64
#define NB 296
#define NT 256
#define GT (NB * NT)
#define NWARPS (GT / 32)

// ---------------- static device scratch ----------------
__device__ int d_cnt[NN];
__device__ int d_rowptr[NN + 1];
__device__ int d_cursor[NN];
__device__ int d_csr_src[EE];
__device__ int d_blocksums[128];
__device__ float d_hA[NN * CWD];
__device__ float d_hB[NN * CWD];
__device__ float d_xw[NN * CWD];
__device__ float d_score[NN];
__device__ float d_dis[NN];
__device__ int d_c2oA[NN];
__device__ int d_c2oB[NN];
__device__ int d_o2c[NN];
__device__ int d_oldidx[NN];
__device__ unsigned d_thresh[GB];
__device__ int d_quota[GB];
__device__ int d_ctr[GB];
__device__ int d_eq[GB];
__device__ unsigned d_romax[4 * GB * CWD];
__device__ float d_rosum[4 * GB * CWD];
__device__ float d_WT[4][CWD * CWD];

// grid barrier state
__device__ int g_bar_count;
__device__ volatile int g_bar_gen;

__device__ __forceinline__ unsigned fkey(float f) {
    unsigned b = __float_as_uint(f);
    return (b & 0x80000000u) ? ~b : (b | 0x80000000u);
}
__device__ __forceinline__ float unfkey(unsigned u) {
    unsigned b = (u & 0x80000000u) ? (u & 0x7fffffffu) : ~u;
    return __uint_as_float(b);
}

__device__ __forceinline__ void gridbar() {
    __syncthreads();
    if (threadIdx.x == 0) {
        int g = g_bar_gen;
        __threadfence();
        if (atomicAdd(&g_bar_count, 1) == NB - 1) {
            g_bar_count = 0;
            __threadfence();
            g_bar_gen = g + 1;
        } else {
            while (g_bar_gen == g) { }
        }
        __threadfence();
    }
    __syncthreads();
}

__device__ __forceinline__ int wscan_incl(int v, int lane) {
    int incl = v;
    #pragma unroll
    for (int off = 1; off < 32; off <<= 1) {
        int n = __shfl_up_sync(0xffffffffu, incl, off);
        if (lane >= off) incl += n;
    }
    return incl;
}

// ---------------- the megakernel ----------------
__global__ void __launch_bounds__(NT, 2) mega_kernel(
    const float* __restrict__ x, const int* __restrict__ ei,
    const float* __restrict__ Wl1, const float* __restrict__ bl1, const float* __restrict__ Wr1,
    const float* __restrict__ Wl2, const float* __restrict__ bl2, const float* __restrict__ Wr2,
    const float* __restrict__ W4, const float* __restrict__ b4,
    const float* __restrict__ W5, const float* __restrict__ b5,
    const float* __restrict__ wp1, const float* __restrict__ wp2,
    const float* __restrict__ wp4, const float* __restrict__ wp5,
    const float* __restrict__ Wa, const float* __restrict__ ba,
    const float* __restrict__ Wb, const float* __restrict__ bb,
    const float* __restrict__ Wc, const float* __restrict__ bc,
    float* __restrict__ out)
{
    __shared__ float s_f[4608];   // 18KB, aliased per phase
    __shared__ unsigned s_pref;
    __shared__ int s_rem;
    int* s_i = (int*)s_f;
    unsigned* s_u = (unsigned*)s_f;

    const int t = threadIdx.x;
    const int lane = t & 31;
    const int w = t >> 5;
    const int gtid = blockIdx.x * NT + t;
    const int gwarp = gtid >> 5;
    const int* src = ei;
    const int* dst = ei + EE;

    // ---- ph0: init + weight transpose ----
    for (int i = gtid; i < NN; i += GT) { d_cnt[i] = 0; d_c2oA[i] = i; }
    for (int i = gtid; i < 4 * GB * CWD; i += GT) { d_romax[i] = 0u; d_rosum[i] = 0.f; }
    for (int i = gtid; i < 4 * 4096; i += GT) {
        int slot = i >> 12, j = i & 4095;
        const float* W = slot == 0 ? Wl2 : slot == 1 ? Wr2 : slot == 2 ? W4 : W5;
        int r = j >> 6, c = j & 63;
        d_WT[slot][c * 64 + r] = W[j];
    }
    gridbar();

    // ---- ph1: histogram ----
    for (int e = gtid; e < EE; e += GT) atomicAdd(&d_cnt[dst[e]], 1);
    gridbar();

    // ---- ph2: per-chunk scan (128 chunks of 1024, blocks 0..127) ----
    if (blockIdx.x < 128) {
        int base = blockIdx.x * 1024;
        int i0 = base + t * 4;
        int v0 = d_cnt[i0], v1 = d_cnt[i0 + 1], v2 = d_cnt[i0 + 2], v3 = d_cnt[i0 + 3];
        int s = v0 + v1 + v2 + v3;
        int incl = wscan_incl(s, lane);
        if (lane == 31) s_i[w] = incl;
        __syncthreads();
        if (t == 0) {
            int acc = 0;
            #pragma unroll
            for (int ww = 0; ww < 8; ww++) { int tmp = s_i[ww]; s_i[ww] = acc; acc += tmp; }
        }
        __syncthreads();
        int ex = s_i[w] + incl - s;
        d_rowptr[i0] = ex;
        d_rowptr[i0 + 1] = ex + v0;
        d_rowptr[i0 + 2] = ex + v0 + v1;
        d_rowptr[i0 + 3] = ex + v0 + v1 + v2;
        if (t == NT - 1) d_blocksums[blockIdx.x] = ex + s;
    }
    gridbar();

    // ---- ph3: scan of 128 blocksums (block 0, warp 0) ----
    if (blockIdx.x == 0 && t < 32) {
        int i0 = lane * 4;
        int v0 = d_blocksums[i0], v1 = d_blocksums[i0 + 1], v2 = d_blocksums[i0 + 2], v3 = d_blocksums[i0 + 3];
        int s = v0 + v1 + v2 + v3;
        int incl = wscan_incl(s, lane);
        int ex = incl - s;
        d_blocksums[i0] = ex;
        d_blocksums[i0 + 1] = ex + v0;
        d_blocksums[i0 + 2] = ex + v0 + v1;
        d_blocksums[i0 + 3] = ex + v0 + v1 + v2;
    }
    gridbar();

    // ---- ph4: add chunk offsets ----
    for (int i = gtid; i < NN; i += GT) {
        int r = d_rowptr[i] + d_blocksums[i >> 10];
        d_rowptr[i] = r;
        d_cursor[i] = r;
    }
    if (gtid == 0) d_rowptr[NN] = EE;
    gridbar();

    // ---- ph5: scatter edges ----
    for (int e = gtid; e < EE; e += GT) {
        int p = atomicAdd(&d_cursor[dst[e]], 1);
        d_csr_src[p] = src[e];
    }
    gridbar();

    // ---- ph6: conv1 SAGE (2->64) ----
    {
        const float2* x2 = (const float2*)x;
        for (int n = gwarp; n < NN; n += NWARPS) {
            int row = d_rowptr[n], end = d_rowptr[n + 1];
            float a0 = 0.f, a1 = 0.f;
            for (int e = row + lane; e < end; e += 32) {
                float2 v = x2[d_csr_src[e]];
                a0 += v.x; a1 += v.y;
            }
            for (int o = 16; o; o >>= 1) {
                a0 += __shfl_xor_sync(0xffffffffu, a0, o);
                a1 += __shfl_xor_sync(0xffffffffu, a1, o);
            }
            float deg = (float)(end - row);
            float inv = deg > 0.f ? 1.f / deg : 0.f;
            float m0 = a0 * inv, m1 = a1 * inv;
            float2 xv = x2[n];
            int d0 = lane, d1 = lane + 32;
            float o0 = Wl1[d0 * 2] * m0 + Wl1[d0 * 2 + 1] * m1 + bl1[d0] + Wr1[d0 * 2] * xv.x + Wr1[d0 * 2 + 1] * xv.y;
            float o1 = Wl1[d1 * 2] * m0 + Wl1[d1 * 2 + 1] * m1 + bl1[d1] + Wr1[d1 * 2] * xv.x + Wr1[d1 * 2 + 1] * xv.y;
            o0 = fmaxf(o0, 0.f); o1 = fmaxf(o1, 0.f);
            d_hA[n * 64 + d0] = o0;
            d_hA[n * 64 + d1] = o1;
            float w0 = wp1[d0], w1 = wp1[d1];
            float sd = o0 * w0 + o1 * w1, nw = w0 * w0 + w1 * w1;
            for (int o = 16; o; o >>= 1) {
                sd += __shfl_xor_sync(0xffffffffu, sd, o);
                nw += __shfl_xor_sync(0xffffffffu, nw, o);
            }
            if (lane == 0) d_score[n] = tanhf(sd * rsqrtf(nw));
        }
    }
    gridbar();

    // ================= 4 stages of pool / conv =================
    #pragma unroll 1
    for (int stage = 0; stage < 4; stage++) {
        // stage params
        int m = 16384 >> stage;            // nodes per graph before pool
        int k = m >> 1;                    // after pool
        int shift = 14 - stage;
        int flip = stage & 1;              // 0: read A write B; 1: read B write A

        // ---- select: exact k-th threshold per graph (blocks 0..7) ----
        if (blockIdx.x < GB) {
            int b = blockIdx.x;
            int base = b * m;
            if (t == 0) { s_pref = 0u; s_rem = k; }
            __syncthreads();
            for (int p = 3; p >= 0; p--) {
                if (t < 256) s_u[t] = 0;
                __syncthreads();
                unsigned pref = s_pref;
                int hs = (p + 1) * 8;
                for (int i = t; i < m; i += NT) {
                    unsigned u = fkey(d_score[base + i]);
                    bool cand = (p == 3) || ((u >> hs) == (pref >> hs));
                    if (cand) atomicAdd(&s_u[(u >> (p * 8)) & 255], 1u);
                }
                __syncthreads();
                if (t == 0) {
                    int rem = s_rem;
                    unsigned c = 0;
                    for (int bb = 255; bb >= 0; bb--) {
                        if (c + s_u[bb] >= (unsigned)rem) {
                            s_pref = pref | ((unsigned)bb << (p * 8));
                            s_rem = rem - (int)c;
                            break;
                        }
                        c += s_u[bb];
                    }
                }
                __syncthreads();
            }
            if (t == 0) {
                d_thresh[b] = s_pref;
                d_quota[b] = s_rem;
                d_ctr[b] = 0;
                d_eq[b] = 0;
            }
        }
        gridbar();

        // ---- compact ----
        for (int c = gtid; c < GB * m; c += GT) {
            int b = c >> shift;
            unsigned u = fkey(d_score[c]);
            unsigned th = d_thresh[b];
            const int* oldm = flip ? d_c2oB : d_c2oA;
            int* newm = flip ? d_c2oA : d_c2oB;
            bool keep = u > th;
            if (!keep && u == th) keep = (atomicAdd(&d_eq[b], 1) < d_quota[b]);
            int orig = oldm[c];
            if (keep) {
                int slot = atomicAdd(&d_ctr[b], 1);
                int nc = b * k + slot;
                newm[nc] = orig;
                d_o2c[orig] = nc;
                d_oldidx[nc] = c;
            } else {
                d_o2c[orig] = -1;
            }
        }
        gridbar();

        // ---- pool copy + fused readout partials ----
        {
            int ntiles = GB * k / 16;   // 16 nodes per tile (one per warp... NT/32=8 warps → 2 nodes/warp)
            // 8 warps per block, each warp handles 2 nodes of the 16-node tile
            for (int tile = blockIdx.x; tile < ntiles; tile += NB) {
                #pragma unroll
                for (int q = 0; q < 2; q++) {
                    int r = w * 2 + q;           // 0..15
                    int gw2 = tile * 16 + r;
                    int oldc = d_oldidx[gw2];
                    float v = d_score[oldc];
                    float2 h = *(const float2*)&d_hA[oldc * 64 + 2 * lane];
                    float v0 = h.x * v, v1 = h.y * v;
                    *(float2*)&d_hB[gw2 * 64 + 2 * lane] = make_float2(v0, v1);
                    s_f[r * 64 + 2 * lane] = v0;
                    s_f[r * 64 + 2 * lane + 1] = v1;
                }
                __syncthreads();
                if (t < 64) {
                    float mx = s_f[t], sm = 0.f;
                    #pragma unroll
                    for (int rr = 0; rr < 16; rr++) {
                        float f = s_f[rr * 64 + t];
                        mx = fmaxf(mx, f);
                        sm += f;
                    }
                    int b = (tile * 16) / k;
                    int off = stage * GB * 64 + b * 64 + t;
                    atomicMax(&d_romax[off], fkey(mx));
                    atomicAdd(&d_rosum[off], sm);
                }
                __syncthreads();
            }
        }
        gridbar();

        if (stage == 3) break;   // last pool: straight to MLP

        int M = GB * k;                       // live nodes for the conv
        const int* c2o = flip ? d_c2oA : d_c2oB;  // current map written by this stage's compact

        if (stage == 0) {
            // ======== SAGE2: agg then transform ========
            for (int n = gwarp; n < M; n += NWARPS) {
                int o = c2o[n];
                int row = d_rowptr[o], end = d_rowptr[o + 1];
                float a0 = 0.f, a1 = 0.f;
                int cnt = 0;
                for (int base = row; base < end; base += 32) {
                    int e = base + lane;
                    int sc = -1;
                    if (e < end) sc = d_o2c[d_csr_src[e]];
                    unsigned liveb = __ballot_sync(0xffffffffu, sc >= 0);
                    cnt += __popc(liveb);
                    while (liveb) {
                        int j = __ffs(liveb) - 1;
                        liveb &= liveb - 1;
                        int scj = __shfl_sync(0xffffffffu, sc, j);
                        float2 v = *(const float2*)&d_hB[scj * 64 + 2 * lane];
                        a0 += v.x; a1 += v.y;
                    }
                }
                float invc = cnt ? 1.f / (float)cnt : 0.f;
                *(float2*)&d_xw[n * 64 + 2 * lane] = make_float2(a0 * invc, a1 * invc);
            }
            gridbar();
            // transform: 4 nodes per warp iteration
            {
                const float* WlT = d_WT[0];
                const float* WrT = d_WT[1];
                float b0 = bl2[lane], b1 = bl2[lane + 32];
                float w0 = wp2[lane], w1 = wp2[lane + 32];
                float nw = w0 * w0 + w1 * w1;
                for (int o = 16; o; o >>= 1) nw += __shfl_xor_sync(0xffffffffu, nw, o);
                float rn = rsqrtf(nw);
                for (int quad = gwarp; quad < M / 4; quad += NWARPS) {
                    int n0 = quad * 4;
                    float mA[4], mB[4], hA[4], hB[4], o0[4], o1[4];
                    #pragma unroll
                    for (int q = 0; q < 4; q++) {
                        int n = n0 + q;
                        mA[q] = d_xw[n * 64 + lane];
                        mB[q] = d_xw[n * 64 + lane + 32];
                        hA[q] = d_hB[n * 64 + lane];
                        hB[q] = d_hB[n * 64 + lane + 32];
                        o0[q] = 0.f; o1[q] = 0.f;
                    }
                    #pragma unroll 4
                    for (int j = 0; j < 32; j++) {
                        float wl0 = __ldg(&WlT[j * 64 + lane]), wl1 = __ldg(&WlT[j * 64 + lane + 32]);
                        float wr0 = __ldg(&WrT[j * 64 + lane]), wr1 = __ldg(&WrT[j * 64 + lane + 32]);
                        #pragma unroll
                        for (int q = 0; q < 4; q++) {
                            float mj = __shfl_sync(0xffffffffu, mA[q], j);
                            float hj = __shfl_sync(0xffffffffu, hA[q], j);
                            o0[q] += wl0 * mj + wr0 * hj;
                            o1[q] += wl1 * mj + wr1 * hj;
                        }
                    }
                    #pragma unroll 4
                    for (int j = 32; j < 64; j++) {
                        float wl0 = __ldg(&WlT[j * 64 + lane]), wl1 = __ldg(&WlT[j * 64 + lane + 32]);
                        float wr0 = __ldg(&WrT[j * 64 + lane]), wr1 = __ldg(&WrT[j * 64 + lane + 32]);
                        #pragma unroll
                        for (int q = 0; q < 4; q++) {
                            float mj = __shfl_sync(0xffffffffu, mB[q], j - 32);
                            float hj = __shfl_sync(0xffffffffu, hB[q], j - 32);
                            o0[q] += wl0 * mj + wr0 * hj;
                            o1[q] += wl1 * mj + wr1 * hj;
                        }
                    }
                    #pragma unroll
                    for (int q = 0; q < 4; q++) {
                        int n = n0 + q;
                        float r0 = fmaxf(o0[q] + b0, 0.f);
                        float r1 = fmaxf(o1[q] + b1, 0.f);
                        d_hA[n * 64 + lane] = r0;
                        d_hA[n * 64 + lane + 32] = r1;
                        float sd = r0 * w0 + r1 * w1;
                        for (int o = 16; o; o >>= 1) sd += __shfl_xor_sync(0xffffffffu, sd, o);
                        if (lane == 0) d_score[n] = tanhf(sd * rn);
                    }
                }
            }
            gridbar();
        } else {
            // ======== GCN (stages 1,2): xw transform + degree, then aggregate ========
            int slot = stage + 1;   // stage1 -> W4(slot2), stage2 -> W5(slot3)
            const float* bias = (stage == 1) ? b4 : b5;
            const float* wp = (stage == 1) ? wp4 : wp5;
            {
                const float* WT = d_WT[slot];
                for (int quad = gwarp; quad < M / 4; quad += NWARPS) {
                    int n0 = quad * 4;
                    float hA[4], hB[4], o0[4], o1[4];
                    #pragma unroll
                    for (int q = 0; q < 4; q++) {
                        int n = n0 + q;
                        hA[q] = d_hB[n * 64 + lane];
                        hB[q] = d_hB[n * 64 + lane + 32];
                        o0[q] = 0.f; o1[q] = 0.f;
                    }
                    #pragma unroll 4
                    for (int j = 0; j < 32; j++) {
                        float w0 = __ldg(&WT[j * 64 + lane]), w1 = __ldg(&WT[j * 64 + lane + 32]);
                        #pragma unroll
                        for (int q = 0; q < 4; q++) {
                            float hj = __shfl_sync(0xffffffffu, hA[q], j);
                            o0[q] += w0 * hj;
                            o1[q] += w1 * hj;
                        }
                    }
                    #pragma unroll 4
                    for (int j = 32; j < 64; j++) {
                        float w0 = __ldg(&WT[j * 64 + lane]), w1 = __ldg(&WT[j * 64 + lane + 32]);
                        #pragma unroll
                        for (int q = 0; q < 4; q++) {
                            float hj = __shfl_sync(0xffffffffu, hB[q], j - 32);
                            o0[q] += w0 * hj;
                            o1[q] += w1 * hj;
                        }
                    }
                    #pragma unroll
                    for (int q = 0; q < 4; q++) {
                        int n = n0 + q;
                        d_xw[n * 64 + lane] = o0[q];
                        d_xw[n * 64 + lane + 32] = o1[q];
                        int o = c2o[n];
                        int row = d_rowptr[o], end = d_rowptr[o + 1];
                        int cnt = 0;
                        for (int base = row; base < end; base += 32) {
                            int e = base + lane;
                            bool live = false;
                            if (e < end) live = (d_o2c[d_csr_src[e]] >= 0);
                            cnt += __popc(__ballot_sync(0xffffffffu, live));
                        }
                        if (lane == 0) d_dis[n] = rsqrtf(1.f + (float)cnt);
                    }
                }
            }
            gridbar();
            // aggregate + epilogue
            for (int n = gwarp; n < M; n += NWARPS) {
                int o = c2o[n];
                float dd = d_dis[n];
                int row = d_rowptr[o], end = d_rowptr[o + 1];
                float a0 = 0.f, a1 = 0.f;
                for (int base = row; base < end; base += 32) {
                    int e = base + lane;
                    int sc = -1;
                    float ds = 0.f;
                    if (e < end) {
                        sc = d_o2c[d_csr_src[e]];
                        if (sc >= 0) ds = d_dis[sc];
                    }
                    unsigned liveb = __ballot_sync(0xffffffffu, sc >= 0);
                    while (liveb) {
                        int j = __ffs(liveb) - 1;
                        liveb &= liveb - 1;
                        int scj = __shfl_sync(0xffffffffu, sc, j);
                        float dsj = __shfl_sync(0xffffffffu, ds, j);
                        float2 v = *(const float2*)&d_xw[scj * 64 + 2 * lane];
                        a0 += v.x * dsj;
                        a1 += v.y * dsj;
                    }
                }
                a0 *= dd; a1 *= dd;
                float2 self = *(const float2*)&d_xw[n * 64 + 2 * lane];
                float o0 = a0 + self.x * dd * dd + bias[2 * lane];
                float o1 = a1 + self.y * dd * dd + bias[2 * lane + 1];
                o0 = fmaxf(o0, 0.f); o1 = fmaxf(o1, 0.f);
                *(float2*)&d_hA[n * 64 + 2 * lane] = make_float2(o0, o1);
                float w0 = wp[2 * lane], w1 = wp[2 * lane + 1];
                float sd = o0 * w0 + o1 * w1, nw = w0 * w0 + w1 * w1;
                for (int s = 16; s; s >>= 1) {
                    sd += __shfl_xor_sync(0xffffffffu, sd, s);
                    nw += __shfl_xor_sync(0xffffffffu, nw, s);
                }
                if (lane == 0) d_score[n] = tanhf(sd * rsqrtf(nw));
            }
            gridbar();
        }
    }

    // ---- final MLP + softmax (block 0) ----
    if (blockIdx.x == 0) {
        float* zs = s_f;
        float* za = s_f + 1024;
        float* zb = s_f + 2048;
        float* zc = s_f + 2560;
        const float invk[4] = {1.f / 8192.f, 1.f / 4096.f, 1.f / 2048.f, 1.f / 1024.f};
        for (int q = t; q < 1024; q += NT) {
            int b = q >> 7, d = q & 127;
            float acc = 0.f;
            if (d < 64) {
                #pragma unroll
                for (int st = 0; st < 4; st++)
                    acc += unfkey(d_romax[st * GB * 64 + b * 64 + d]);
            } else {
                #pragma unroll
                for (int st = 0; st < 4; st++)
                    acc += d_rosum[st * GB * 64 + b * 64 + (d - 64)] * invk[st];
            }
            zs[q] = acc;
        }
        __syncthreads();
        for (int q = t; q < 1024; q += NT) {
            int b = q >> 7, o = q & 127;
            float a = ba[o];
            const float* wv = Wa + o * 128;
            const float* z = zs + b * 128;
            for (int j = 0; j < 128; j++) a += wv[j] * z[j];
            za[q] = fmaxf(a, 0.f);
        }
        __syncthreads();
        for (int q = t; q < 512; q += NT) {
            int b = q >> 6, o = q & 63;
            float a = bb[o];
            for (int j = 0; j < 128; j++) a += Wb[o * 128 + j] * za[b * 128 + j];
            zb[q] = fmaxf(a, 0.f);
        }
        __syncthreads();
        for (int q = t; q < 2048; q += NT) {
            int b = q >> 8, o = q & 255;
            float a = bc[o];
            for (int j = 0; j < 64; j++) a += Wc[o * 64 + j] * zb[b * 64 + j];
            zc[q] = a;
        }
        __syncthreads();
        {
            float mx = -3.4e38f;
            for (int i = lane; i < 256; i += 32) mx = fmaxf(mx, zc[w * 256 + i]);
            for (int o = 16; o; o >>= 1) mx = fmaxf(mx, __shfl_xor_sync(0xffffffffu, mx, o));
            float s = 0.f;
            for (int i = lane; i < 256; i += 32) {
                float e = expf(zc[w * 256 + i] - mx);
                zc[w * 256 + i] = e;
                s += e;
            }
            for (int o = 16; o; o >>= 1) s += __shfl_xor_sync(0xffffffffu, s, o);
            float inv = 1.f / s;
            for (int i = lane; i < 256; i += 32) out[w * 256 + i] = zc[w * 256 + i] * inv;
        }
    }
}

// ---------------- launch ----------------
extern "C" void kernel_launch(void* const* d_in, const int* in_sizes, int n_in,
                              void* d_out, int out_size) {
    mega_kernel<<<NB, NT>>>(
        (const float*)d_in[0], (const int*)d_in[1],
        (const float*)d_in[2], (const float*)d_in[3], (const float*)d_in[4],
        (const float*)d_in[5], (const float*)d_in[6], (const float*)d_in[7],
        (const float*)d_in[8], (const float*)d_in[9],
        (const float*)d_in[10], (const float*)d_in[11],
        (const float*)d_in[12], (const float*)d_in[13],
        (const float*)d_in[14], (const float*)d_in[15],
        (const float*)d_in[16], (const float*)d_in[17],
        (const float*)d_in[18], (const float*)d_in[19],
        (const float*)d_in[20], (const float*)d_in[21],
        (float*)d_out);
}

// round 6
// speedup vs baseline: 1.1378x; 1.1378x over previous
#include <cuda_runtime.h>

#define NN 131072
#define EE 2097152
#define GB 8
#define CWD 64
#define NB 592
#define NT 256
#define GT (NB * NT)
#define NWARPS (GT / 32)

// ---------------- static device scratch ----------------
__device__ int d_cnt[NN];
__device__ int d_rowptr[NN + 1];
__device__ int d_cursor[NN];
__device__ int d_csr_src[EE];
__device__ int d_blocksums[128];
__device__ float d_hA[NN * CWD];
__device__ float d_hB[NN * CWD];
__device__ float d_xw[NN * CWD];
__device__ float d_score[NN];
__device__ float d_dis[NN];
__device__ int d_c2oA[NN];
__device__ int d_c2oB[NN];
__device__ int d_o2c[NN];
__device__ int d_oldidx[NN];
__device__ unsigned d_thresh[GB];
__device__ int d_quota[GB];
__device__ int d_ctr[GB];
__device__ int d_eq[GB];
__device__ unsigned d_romax[4 * GB * CWD];
__device__ float d_rosum[4 * GB * CWD];
__device__ float d_WT[4][CWD * CWD];

// grid barrier state
__device__ int g_bar_count;
__device__ volatile int g_bar_gen;

__device__ __forceinline__ unsigned fkey(float f) {
    unsigned b = __float_as_uint(f);
    return (b & 0x80000000u) ? ~b : (b | 0x80000000u);
}
__device__ __forceinline__ float unfkey(unsigned u) {
    unsigned b = (u & 0x80000000u) ? (u & 0x7fffffffu) : ~u;
    return __uint_as_float(b);
}

__device__ __forceinline__ void gridbar() {
    __syncthreads();
    if (threadIdx.x == 0) {
        int g = g_bar_gen;
        __threadfence();
        if (atomicAdd(&g_bar_count, 1) == NB - 1) {
            g_bar_count = 0;
            __threadfence();
            g_bar_gen = g + 1;
        } else {
            while (g_bar_gen == g) { }
        }
        __threadfence();
    }
    __syncthreads();
}

__device__ __forceinline__ int wscan_incl(int v, int lane) {
    int incl = v;
    #pragma unroll
    for (int off = 1; off < 32; off <<= 1) {
        int n = __shfl_up_sync(0xffffffffu, incl, off);
        if (lane >= off) incl += n;
    }
    return incl;
}

// ---------------- the megakernel ----------------
__global__ void __launch_bounds__(NT, 4) mega_kernel(
    const float* __restrict__ x, const int* __restrict__ ei,
    const float* __restrict__ Wl1, const float* __restrict__ bl1, const float* __restrict__ Wr1,
    const float* __restrict__ Wl2, const float* __restrict__ bl2, const float* __restrict__ Wr2,
    const float* __restrict__ W4, const float* __restrict__ b4,
    const float* __restrict__ W5, const float* __restrict__ b5,
    const float* __restrict__ wp1, const float* __restrict__ wp2,
    const float* __restrict__ wp4, const float* __restrict__ wp5,
    const float* __restrict__ Wa, const float* __restrict__ ba,
    const float* __restrict__ Wb, const float* __restrict__ bb,
    const float* __restrict__ Wc, const float* __restrict__ bc,
    float* __restrict__ out)
{
    __shared__ float s_f[4608];   // 18KB, aliased per phase
    __shared__ unsigned s_pref;
    __shared__ int s_rem;
    int* s_i = (int*)s_f;
    unsigned* s_u = (unsigned*)s_f;

    const int t = threadIdx.x;
    const int lane = t & 31;
    const int w = t >> 5;
    const int gtid = blockIdx.x * NT + t;
    const int gwarp = gtid >> 5;
    const int* src = ei;
    const int* dst = ei + EE;

    // ---- ph0: init + weight transpose ----
    for (int i = gtid; i < NN; i += GT) { d_cnt[i] = 0; d_c2oA[i] = i; }
    for (int i = gtid; i < 4 * GB * CWD; i += GT) { d_romax[i] = 0u; d_rosum[i] = 0.f; }
    for (int i = gtid; i < 4 * 4096; i += GT) {
        int slot = i >> 12, j = i & 4095;
        const float* W = slot == 0 ? Wl2 : slot == 1 ? Wr2 : slot == 2 ? W4 : W5;
        int r = j >> 6, c = j & 63;
        d_WT[slot][c * 64 + r] = W[j];
    }
    gridbar();

    // ---- ph1: histogram ----
    for (int e = gtid; e < EE; e += GT) atomicAdd(&d_cnt[dst[e]], 1);
    gridbar();

    // ---- ph2: per-chunk scan (128 chunks of 1024, blocks 0..127) ----
    if (blockIdx.x < 128) {
        int base = blockIdx.x * 1024;
        int i0 = base + t * 4;
        int v0 = d_cnt[i0], v1 = d_cnt[i0 + 1], v2 = d_cnt[i0 + 2], v3 = d_cnt[i0 + 3];
        int s = v0 + v1 + v2 + v3;
        int incl = wscan_incl(s, lane);
        if (lane == 31) s_i[w] = incl;
        __syncthreads();
        if (t == 0) {
            int acc = 0;
            #pragma unroll
            for (int ww = 0; ww < 8; ww++) { int tmp = s_i[ww]; s_i[ww] = acc; acc += tmp; }
        }
        __syncthreads();
        int ex = s_i[w] + incl - s;
        d_rowptr[i0] = ex;
        d_rowptr[i0 + 1] = ex + v0;
        d_rowptr[i0 + 2] = ex + v0 + v1;
        d_rowptr[i0 + 3] = ex + v0 + v1 + v2;
        if (t == NT - 1) d_blocksums[blockIdx.x] = ex + s;
    }
    gridbar();

    // ---- ph3: scan of 128 blocksums (block 0, warp 0) ----
    if (blockIdx.x == 0 && t < 32) {
        int i0 = lane * 4;
        int v0 = d_blocksums[i0], v1 = d_blocksums[i0 + 1], v2 = d_blocksums[i0 + 2], v3 = d_blocksums[i0 + 3];
        int s = v0 + v1 + v2 + v3;
        int incl = wscan_incl(s, lane);
        int ex = incl - s;
        d_blocksums[i0] = ex;
        d_blocksums[i0 + 1] = ex + v0;
        d_blocksums[i0 + 2] = ex + v0 + v1;
        d_blocksums[i0 + 3] = ex + v0 + v1 + v2;
    }
    gridbar();

    // ---- ph4: add chunk offsets ----
    for (int i = gtid; i < NN; i += GT) {
        int r = d_rowptr[i] + d_blocksums[i >> 10];
        d_rowptr[i] = r;
        d_cursor[i] = r;
    }
    if (gtid == 0) d_rowptr[NN] = EE;
    gridbar();

    // ---- ph5: scatter edges ----
    for (int e = gtid; e < EE; e += GT) {
        int p = atomicAdd(&d_cursor[dst[e]], 1);
        d_csr_src[p] = src[e];
    }
    gridbar();

    // ---- ph6: conv1 SAGE (2->64) ----
    {
        const float2* x2 = (const float2*)x;
        for (int n = gwarp; n < NN; n += NWARPS) {
            int row = d_rowptr[n], end = d_rowptr[n + 1];
            float a0 = 0.f, a1 = 0.f;
            for (int e = row + lane; e < end; e += 32) {
                float2 v = x2[d_csr_src[e]];
                a0 += v.x; a1 += v.y;
            }
            for (int o = 16; o; o >>= 1) {
                a0 += __shfl_xor_sync(0xffffffffu, a0, o);
                a1 += __shfl_xor_sync(0xffffffffu, a1, o);
            }
            float deg = (float)(end - row);
            float inv = deg > 0.f ? 1.f / deg : 0.f;
            float m0 = a0 * inv, m1 = a1 * inv;
            float2 xv = x2[n];
            int d0 = lane, d1 = lane + 32;
            float o0 = Wl1[d0 * 2] * m0 + Wl1[d0 * 2 + 1] * m1 + bl1[d0] + Wr1[d0 * 2] * xv.x + Wr1[d0 * 2 + 1] * xv.y;
            float o1 = Wl1[d1 * 2] * m0 + Wl1[d1 * 2 + 1] * m1 + bl1[d1] + Wr1[d1 * 2] * xv.x + Wr1[d1 * 2 + 1] * xv.y;
            o0 = fmaxf(o0, 0.f); o1 = fmaxf(o1, 0.f);
            d_hA[n * 64 + d0] = o0;
            d_hA[n * 64 + d1] = o1;
            float w0 = wp1[d0], w1 = wp1[d1];
            float sd = o0 * w0 + o1 * w1, nw = w0 * w0 + w1 * w1;
            for (int o = 16; o; o >>= 1) {
                sd += __shfl_xor_sync(0xffffffffu, sd, o);
                nw += __shfl_xor_sync(0xffffffffu, nw, o);
            }
            if (lane == 0) d_score[n] = tanhf(sd * rsqrtf(nw));
        }
    }
    gridbar();

    // ================= 4 stages of pool / conv =================
    #pragma unroll 1
    for (int stage = 0; stage < 4; stage++) {
        int m = 16384 >> stage;
        int k = m >> 1;
        int shift = 14 - stage;
        int flip = stage & 1;

        // ---- select: exact k-th threshold per graph (blocks 0..7) ----
        if (blockIdx.x < GB) {
            int b = blockIdx.x;
            int base = b * m;
            if (t == 0) { s_pref = 0u; s_rem = k; }
            __syncthreads();
            for (int p = 3; p >= 0; p--) {
                if (t < 256) s_u[t] = 0;
                __syncthreads();
                unsigned pref = s_pref;
                int hs = (p + 1) * 8;
                for (int i = t; i < m; i += NT) {
                    unsigned u = fkey(d_score[base + i]);
                    bool cand = (p == 3) || ((u >> hs) == (pref >> hs));
                    if (cand) atomicAdd(&s_u[(u >> (p * 8)) & 255], 1u);
                }
                __syncthreads();
                if (t == 0) {
                    int rem = s_rem;
                    unsigned c = 0;
                    for (int bb = 255; bb >= 0; bb--) {
                        if (c + s_u[bb] >= (unsigned)rem) {
                            s_pref = pref | ((unsigned)bb << (p * 8));
                            s_rem = rem - (int)c;
                            break;
                        }
                        c += s_u[bb];
                    }
                }
                __syncthreads();
            }
            if (t == 0) {
                d_thresh[b] = s_pref;
                d_quota[b] = s_rem;
                d_ctr[b] = 0;
                d_eq[b] = 0;
            }
        }
        gridbar();

        // ---- compact ----
        for (int c = gtid; c < GB * m; c += GT) {
            int b = c >> shift;
            unsigned u = fkey(d_score[c]);
            unsigned th = d_thresh[b];
            const int* oldm = flip ? d_c2oB : d_c2oA;
            int* newm = flip ? d_c2oA : d_c2oB;
            bool keep = u > th;
            if (!keep && u == th) keep = (atomicAdd(&d_eq[b], 1) < d_quota[b]);
            int orig = oldm[c];
            if (keep) {
                int slot = atomicAdd(&d_ctr[b], 1);
                int nc = b * k + slot;
                newm[nc] = orig;
                d_o2c[orig] = nc;
                d_oldidx[nc] = c;
            } else {
                d_o2c[orig] = -1;
            }
        }
        gridbar();

        // ---- pool copy + fused readout partials ----
        {
            int ntiles = GB * k / 16;
            for (int tile = blockIdx.x; tile < ntiles; tile += NB) {
                #pragma unroll
                for (int q = 0; q < 2; q++) {
                    int r = w * 2 + q;
                    int gw2 = tile * 16 + r;
                    int oldc = d_oldidx[gw2];
                    float v = d_score[oldc];
                    float2 h = *(const float2*)&d_hA[oldc * 64 + 2 * lane];
                    float v0 = h.x * v, v1 = h.y * v;
                    *(float2*)&d_hB[gw2 * 64 + 2 * lane] = make_float2(v0, v1);
                    s_f[r * 64 + 2 * lane] = v0;
                    s_f[r * 64 + 2 * lane + 1] = v1;
                }
                __syncthreads();
                if (t < 64) {
                    float mx = s_f[t], sm = 0.f;
                    #pragma unroll
                    for (int rr = 0; rr < 16; rr++) {
                        float f = s_f[rr * 64 + t];
                        mx = fmaxf(mx, f);
                        sm += f;
                    }
                    int b = (tile * 16) / k;
                    int off = stage * GB * 64 + b * 64 + t;
                    atomicMax(&d_romax[off], fkey(mx));
                    atomicAdd(&d_rosum[off], sm);
                }
                __syncthreads();
            }
        }
        gridbar();

        if (stage == 3) break;

        int M = GB * k;
        const int* c2o = flip ? d_c2oA : d_c2oB;

        if (stage == 0) {
            // ======== SAGE2: agg then transform ========
            for (int n = gwarp; n < M; n += NWARPS) {
                int o = c2o[n];
                int row = d_rowptr[o], end = d_rowptr[o + 1];
                float a0 = 0.f, a1 = 0.f;
                int cnt = 0;
                for (int base = row; base < end; base += 32) {
                    int e = base + lane;
                    int sc = -1;
                    if (e < end) sc = d_o2c[d_csr_src[e]];
                    unsigned liveb = __ballot_sync(0xffffffffu, sc >= 0);
                    cnt += __popc(liveb);
                    while (liveb) {
                        int j = __ffs(liveb) - 1;
                        liveb &= liveb - 1;
                        int scj = __shfl_sync(0xffffffffu, sc, j);
                        float2 v = *(const float2*)&d_hB[scj * 64 + 2 * lane];
                        a0 += v.x; a1 += v.y;
                    }
                }
                float invc = cnt ? 1.f / (float)cnt : 0.f;
                *(float2*)&d_xw[n * 64 + 2 * lane] = make_float2(a0 * invc, a1 * invc);
            }
            gridbar();
            // transform: 2 nodes per warp iteration (reg-lean for occupancy 4)
            {
                const float* WlT = d_WT[0];
                const float* WrT = d_WT[1];
                float b0 = bl2[lane], b1 = bl2[lane + 32];
                float w0 = wp2[lane], w1 = wp2[lane + 32];
                float nw = w0 * w0 + w1 * w1;
                for (int o = 16; o; o >>= 1) nw += __shfl_xor_sync(0xffffffffu, nw, o);
                float rn = rsqrtf(nw);
                for (int pair = gwarp; pair < M / 2; pair += NWARPS) {
                    int n0 = pair * 2;
                    float mA[2], mB[2], hA[2], hB[2], o0[2], o1[2];
                    #pragma unroll
                    for (int q = 0; q < 2; q++) {
                        int n = n0 + q;
                        mA[q] = d_xw[n * 64 + lane];
                        mB[q] = d_xw[n * 64 + lane + 32];
                        hA[q] = d_hB[n * 64 + lane];
                        hB[q] = d_hB[n * 64 + lane + 32];
                        o0[q] = 0.f; o1[q] = 0.f;
                    }
                    #pragma unroll 4
                    for (int j = 0; j < 32; j++) {
                        float wl0 = __ldg(&WlT[j * 64 + lane]), wl1 = __ldg(&WlT[j * 64 + lane + 32]);
                        float wr0 = __ldg(&WrT[j * 64 + lane]), wr1 = __ldg(&WrT[j * 64 + lane + 32]);
                        #pragma unroll
                        for (int q = 0; q < 2; q++) {
                            float mj = __shfl_sync(0xffffffffu, mA[q], j);
                            float hj = __shfl_sync(0xffffffffu, hA[q], j);
                            o0[q] += wl0 * mj + wr0 * hj;
                            o1[q] += wl1 * mj + wr1 * hj;
                        }
                    }
                    #pragma unroll 4
                    for (int j = 32; j < 64; j++) {
                        float wl0 = __ldg(&WlT[j * 64 + lane]), wl1 = __ldg(&WlT[j * 64 + lane + 32]);
                        float wr0 = __ldg(&WrT[j * 64 + lane]), wr1 = __ldg(&WrT[j * 64 + lane + 32]);
                        #pragma unroll
                        for (int q = 0; q < 2; q++) {
                            float mj = __shfl_sync(0xffffffffu, mB[q], j - 32);
                            float hj = __shfl_sync(0xffffffffu, hB[q], j - 32);
                            o0[q] += wl0 * mj + wr0 * hj;
                            o1[q] += wl1 * mj + wr1 * hj;
                        }
                    }
                    #pragma unroll
                    for (int q = 0; q < 2; q++) {
                        int n = n0 + q;
                        float r0 = fmaxf(o0[q] + b0, 0.f);
                        float r1 = fmaxf(o1[q] + b1, 0.f);
                        d_hA[n * 64 + lane] = r0;
                        d_hA[n * 64 + lane + 32] = r1;
                        float sd = r0 * w0 + r1 * w1;
                        for (int o = 16; o; o >>= 1) sd += __shfl_xor_sync(0xffffffffu, sd, o);
                        if (lane == 0) d_score[n] = tanhf(sd * rn);
                    }
                }
            }
            gridbar();
        } else {
            // ======== GCN (stages 1,2): xw transform + degree, then aggregate ========
            int slot = stage + 1;
            const float* bias = (stage == 1) ? b4 : b5;
            const float* wp = (stage == 1) ? wp4 : wp5;
            {
                const float* WT = d_WT[slot];
                for (int pair = gwarp; pair < M / 2; pair += NWARPS) {
                    int n0 = pair * 2;
                    float hA[2], hB[2], o0[2], o1[2];
                    #pragma unroll
                    for (int q = 0; q < 2; q++) {
                        int n = n0 + q;
                        hA[q] = d_hB[n * 64 + lane];
                        hB[q] = d_hB[n * 64 + lane + 32];
                        o0[q] = 0.f; o1[q] = 0.f;
                    }
                    #pragma unroll 4
                    for (int j = 0; j < 32; j++) {
                        float w0 = __ldg(&WT[j * 64 + lane]), w1 = __ldg(&WT[j * 64 + lane + 32]);
                        #pragma unroll
                        for (int q = 0; q < 2; q++) {
                            float hj = __shfl_sync(0xffffffffu, hA[q], j);
                            o0[q] += w0 * hj;
                            o1[q] += w1 * hj;
                        }
                    }
                    #pragma unroll 4
                    for (int j = 32; j < 64; j++) {
                        float w0 = __ldg(&WT[j * 64 + lane]), w1 = __ldg(&WT[j * 64 + lane + 32]);
                        #pragma unroll
                        for (int q = 0; q < 2; q++) {
                            float hj = __shfl_sync(0xffffffffu, hB[q], j - 32);
                            o0[q] += w0 * hj;
                            o1[q] += w1 * hj;
                        }
                    }
                    #pragma unroll
                    for (int q = 0; q < 2; q++) {
                        int n = n0 + q;
                        d_xw[n * 64 + lane] = o0[q];
                        d_xw[n * 64 + lane + 32] = o1[q];
                        int o = c2o[n];
                        int row = d_rowptr[o], end = d_rowptr[o + 1];
                        int cnt = 0;
                        for (int base = row; base < end; base += 32) {
                            int e = base + lane;
                            bool live = false;
                            if (e < end) live = (d_o2c[d_csr_src[e]] >= 0);
                            cnt += __popc(__ballot_sync(0xffffffffu, live));
                        }
                        if (lane == 0) d_dis[n] = rsqrtf(1.f + (float)cnt);
                    }
                }
            }
            gridbar();
            // aggregate + epilogue
            for (int n = gwarp; n < M; n += NWARPS) {
                int o = c2o[n];
                float dd = d_dis[n];
                int row = d_rowptr[o], end = d_rowptr[o + 1];
                float a0 = 0.f, a1 = 0.f;
                for (int base = row; base < end; base += 32) {
                    int e = base + lane;
                    int sc = -1;
                    float ds = 0.f;
                    if (e < end) {
                        sc = d_o2c[d_csr_src[e]];
                        if (sc >= 0) ds = d_dis[sc];
                    }
                    unsigned liveb = __ballot_sync(0xffffffffu, sc >= 0);
                    while (liveb) {
                        int j = __ffs(liveb) - 1;
                        liveb &= liveb - 1;
                        int scj = __shfl_sync(0xffffffffu, sc, j);
                        float dsj = __shfl_sync(0xffffffffu, ds, j);
                        float2 v = *(const float2*)&d_xw[scj * 64 + 2 * lane];
                        a0 += v.x * dsj;
                        a1 += v.y * dsj;
                    }
                }
                a0 *= dd; a1 *= dd;
                float2 self = *(const float2*)&d_xw[n * 64 + 2 * lane];
                float o0 = a0 + self.x * dd * dd + bias[2 * lane];
                float o1 = a1 + self.y * dd * dd + bias[2 * lane + 1];
                o0 = fmaxf(o0, 0.f); o1 = fmaxf(o1, 0.f);
                *(float2*)&d_hA[n * 64 + 2 * lane] = make_float2(o0, o1);
                float w0 = wp[2 * lane], w1 = wp[2 * lane + 1];
                float sd = o0 * w0 + o1 * w1, nw = w0 * w0 + w1 * w1;
                for (int s = 16; s; s >>= 1) {
                    sd += __shfl_xor_sync(0xffffffffu, sd, s);
                    nw += __shfl_xor_sync(0xffffffffu, nw, s);
                }
                if (lane == 0) d_score[n] = tanhf(sd * rsqrtf(nw));
            }
            gridbar();
        }
    }

    // ---- final MLP + softmax (block 0) ----
    if (blockIdx.x == 0) {
        float* zs = s_f;
        float* za = s_f + 1024;
        float* zb = s_f + 2048;
        float* zc = s_f + 2560;
        const float invk[4] = {1.f / 8192.f, 1.f / 4096.f, 1.f / 2048.f, 1.f / 1024.f};
        for (int q = t; q < 1024; q += NT) {
            int b = q >> 7, d = q & 127;
            float acc = 0.f;
            if (d < 64) {
                #pragma unroll
                for (int st = 0; st < 4; st++)
                    acc += unfkey(d_romax[st * GB * 64 + b * 64 + d]);
            } else {
                #pragma unroll
                for (int st = 0; st < 4; st++)
                    acc += d_rosum[st * GB * 64 + b * 64 + (d - 64)] * invk[st];
            }
            zs[q] = acc;
        }
        __syncthreads();
        for (int q = t; q < 1024; q += NT) {
            int b = q >> 7, o = q & 127;
            float a = ba[o];
            const float* wv = Wa + o * 128;
            const float* z = zs + b * 128;
            for (int j = 0; j < 128; j++) a += wv[j] * z[j];
            za[q] = fmaxf(a, 0.f);
        }
        __syncthreads();
        for (int q = t; q < 512; q += NT) {
            int b = q >> 6, o = q & 63;
            float a = bb[o];
            for (int j = 0; j < 128; j++) a += Wb[o * 128 + j] * za[b * 128 + j];
            zb[q] = fmaxf(a, 0.f);
        }
        __syncthreads();
        for (int q = t; q < 2048; q += NT) {
            int b = q >> 8, o = q & 255;
            float a = bc[o];
            for (int j = 0; j < 64; j++) a += Wc[o * 64 + j] * zb[b * 64 + j];
            zc[q] = a;
        }
        __syncthreads();
        {
            float mx = -3.4e38f;
            for (int i = lane; i < 256; i += 32) mx = fmaxf(mx, zc[w * 256 + i]);
            for (int o = 16; o; o >>= 1) mx = fmaxf(mx, __shfl_xor_sync(0xffffffffu, mx, o));
            float s = 0.f;
            for (int i = lane; i < 256; i += 32) {
                float e = expf(zc[w * 256 + i] - mx);
                zc[w * 256 + i] = e;
                s += e;
            }
            for (int o = 16; o; o >>= 1) s += __shfl_xor_sync(0xffffffffu, s, o);
            float inv = 1.f / s;
            for (int i = lane; i < 256; i += 32) out[w * 256 + i] = zc[w * 256 + i] * inv;
        }
    }
}

// ---------------- launch ----------------
extern "C" void kernel_launch(void* const* d_in, const int* in_sizes, int n_in,
                              void* d_out, int out_size) {
    mega_kernel<<<NB, NT>>>(
        (const float*)d_in[0], (const int*)d_in[1],
        (const float*)d_in[2], (const float*)d_in[3], (const float*)d_in[4],
        (const float*)d_in[5], (const float*)d_in[6], (const float*)d_in[7],
        (const float*)d_in[8], (const float*)d_in[9],
        (const float*)d_in[10], (const float*)d_in[11],
        (const float*)d_in[12], (const float*)d_in[13],
        (const float*)d_in[14], (const float*)d_in[15],
        (const float*)d_in[16], (const float*)d_in[17],
        (const float*)d_in[18], (const float*)d_in[19],
        (const float*)d_in[20], (const float*)d_in[21],
        (float*)d_out);
}